// round 15
// baseline (speedup 1.0000x reference)
#include <cuda_runtime.h>
#include <cstdint>

// ---------------------------------------------------------------------------
// SkipGram negative-sampling: bit-exact JAX threefry gumbel top-k + dot products
// V=100000, D=512, B=1024, C=20, NEG=64
// ---------------------------------------------------------------------------

#define VV   100000
#define DD   512
#define BB   1024
#define CC   20
#define NEG  64
#define CAP  384
#define T0   (-5.0)        // prefilter: mean survivors ~e^5.05 ~ 156/row
#define HASH_CTAS 25       // 25*256*16 = 102400 >= VV

extern "C" __device__ float __nv_logf(float);

// -------- static scratch --------
__device__ float    d_logp[VV];
__device__ unsigned d_thresh[VV];
__device__ int      d_cnt[BB];
__device__ int      d_cand_v[BB * CAP];

// ---------------------------------------------------------------------------
// threefry2x32, key (0,42). Round add forced to IMAD (fma pipe) via opaque
// `one`; alu pipe carries exactly 20 SHF + 20 LOP3 (measured floor).
// ---------------------------------------------------------------------------
#define TFR(r) { x0 = x0 * one + x1; x1 = __funnelshift_l(x1, x1, (r)) ^ x0; }

__device__ __forceinline__ unsigned tf_bits(unsigned ctr, unsigned one) {
    const unsigned ks1 = 42u, ks2 = 0x1BD11BF0u;   // 0x1BD11BDA ^ 42
    unsigned x0 = 0u;
    unsigned x1 = ctr + ks1;
    TFR(13) TFR(15) TFR(26) TFR(6)
    x0 += ks1; x1 += ks2 + 1u;
    TFR(17) TFR(29) TFR(16) TFR(24)
    x0 += ks2; x1 += 2u;
    TFR(13) TFR(15) TFR(26) TFR(6)
    x1 += ks1 + 3u;
    TFR(17) TFR(29) TFR(16) TFR(24)
    x0 += ks1; x1 += ks2 + 4u;
    TFR(13) TFR(15) TFR(26) TFR(6)
    x0 += ks2; x1 += 5u;
    return x0 ^ x1;
}

// ---------------------------------------------------------------------------
// k0: per-word logp (exact f32, used by rescoring) + conservative integer
// prefilter threshold — MUFU path, margin 0.05 in score space plus an 8-ulp
// guard, both strictly enlarging the candidate set. Zeroes cnt.
// ---------------------------------------------------------------------------
__global__ __launch_bounds__(256) void k0_tables(const float* __restrict__ p) {
    int v = blockIdx.x * 256 + threadIdx.x;
    if (v < BB) d_cnt[v] = 0;
    if (v >= VV) return;
    float pf = p[v];
    float lp = __nv_logf(pf);
    d_logp[v] = lp;
    float E = __expf(lp - (float)(T0 - 0.05));
    float ucrit = __expf(-E);
    int m = (int)floorf(ucrit * 8388608.0f) - 8;
    if (m < 0) m = 0;
    if (m > 8388607) m = 8388607;
    d_thresh[v] = ((unsigned)m) << 9;
}

// ---------------------------------------------------------------------------
// k1 (hash + positive dots): grid (HASH_CTAS+3, B), launch_bounds(256,6).
//  x <  HASH_CTAS : hash path — 16 v/thread in 4-hash groups, compute-and-
//                   discard threefry, per-survivor atomicAdd (~0.4/warp).
//  x >= HASH_CTAS : positive-dot CTAs (memory-bound, overlap hashing).
// ---------------------------------------------------------------------------
__global__ __launch_bounds__(256, 6) void k1_fused(unsigned one,
                                                const int* __restrict__ center_ids,
                                                const int* __restrict__ context_ids,
                                                const float* __restrict__ Wc,
                                                float* __restrict__ out) {
    const int b = blockIdx.y;

    if (blockIdx.x >= HASH_CTAS) {
        // ---- positive dots ----
        __shared__ __align__(16) float s_ctr[DD];
        const int k = blockIdx.x - HASH_CTAS;           // 0..2
        const size_t crow = (size_t)center_ids[b] * DD;
        for (int i = threadIdx.x; i < DD; i += 256) s_ctr[i] = Wc[crow + i];
        __syncthreads();
        const int warp = threadIdx.x >> 5;
        const int lane = threadIdx.x & 31;
        const int j = k * 8 + warp;
        if (j < CC) {
            const float4* row4 = (const float4*)(Wc + (size_t)context_ids[b * CC + j] * DD);
            const float4* ctr4 = (const float4*)s_ctr;
            float acc = 0.0f;
#pragma unroll
            for (int t = 0; t < 4; t++) {
                float4 r = row4[lane + 32 * t];
                float4 c = ctr4[lane + 32 * t];
                acc += r.x * c.x + r.y * c.y + r.z * c.z + r.w * c.w;
            }
#pragma unroll
            for (int d2 = 16; d2 > 0; d2 >>= 1)
                acc += __shfl_down_sync(0xFFFFFFFFu, acc, d2);
            if (lane == 0) out[b * CC + j] = acc;
        }
        return;
    }

    // ---- hash path: 16 consecutive v per thread, 4-hash groups ----
    const int tg = blockIdx.x * 256 + threadIdx.x;
    const int v0 = tg * 16;
    if (v0 >= VV) return;                   // VV % 16 == 0: per-thread uniform

    const unsigned base = (unsigned)b * (unsigned)VV + (unsigned)v0;
#pragma unroll
    for (int q = 0; q < 4; q++) {
        const uint4 t = *(const uint4*)&d_thresh[v0 + 4 * q];
        unsigned bits;
        bits = tf_bits(base + (unsigned)(4 * q + 0), one);
        if (bits >= t.x) {
            int pos = atomicAdd(&d_cnt[b], 1);
            if (pos < CAP) d_cand_v[b * CAP + pos] = v0 + 4 * q + 0;
        }
        bits = tf_bits(base + (unsigned)(4 * q + 1), one);
        if (bits >= t.y) {
            int pos = atomicAdd(&d_cnt[b], 1);
            if (pos < CAP) d_cand_v[b * CAP + pos] = v0 + 4 * q + 1;
        }
        bits = tf_bits(base + (unsigned)(4 * q + 2), one);
        if (bits >= t.z) {
            int pos = atomicAdd(&d_cnt[b], 1);
            if (pos < CAP) d_cand_v[b * CAP + pos] = v0 + 4 * q + 2;
        }
        bits = tf_bits(base + (unsigned)(4 * q + 3), one);
        if (bits >= t.w) {
            int pos = atomicAdd(&d_cnt[b], 1);
            if (pos < CAP) d_cand_v[b * CAP + pos] = v0 + 4 * q + 3;
        }
    }
}

// ---------------------------------------------------------------------------
// k2 (fused select + negative dots): one 512-thread CTA per b.
//  1. recompute hash per candidate, exact reference-f32 rescoring
//  2. bitonic top-64 over padded size sz (usually 256; extra warps idle
//     through barriers — cheap)
//     key = ordered(score)<<32 | ~v: score desc, index asc (XLA tie-break)
//  3. 16 warps x 4 rows stream the 64 negative rows of W_context -> per-CTA
//     gather critical path halved vs 8 warps.
// ---------------------------------------------------------------------------
__global__ __launch_bounds__(512) void k2_fused(unsigned one,
                                                const int* __restrict__ center_ids,
                                                const float* __restrict__ Wc,
                                                const float* __restrict__ Wx,
                                                float* __restrict__ out) {
    __shared__ __align__(16) unsigned long long key[CAP < 512 ? 512 : CAP];
    __shared__ __align__(16) float ctr[DD];
    __shared__ __align__(16) int   negs[NEG];
    const int b = blockIdx.x;
    int n = d_cnt[b];
    if (n > CAP) n = CAP;

    int sz = 64;
    while (sz < n) sz <<= 1;               // usually 256

    // center row -> smem (overlaps with candidate rescoring)
    const size_t crow = (size_t)center_ids[b] * DD;
    if (threadIdx.x < DD) ctr[threadIdx.x] = Wc[crow + threadIdx.x];

    for (int s = threadIdx.x; s < sz; s += 512) {
        unsigned long long kk = 0ull;
        if (s < n) {
            int v = d_cand_v[b * CAP + s];
            unsigned bits = tf_bits((unsigned)b * (unsigned)VV + (unsigned)v, one);
            unsigned m = bits >> 9;
            float f  = __fadd_rn(__uint_as_float(m | 0x3f800000u), -1.0f);
            float u  = __fadd_rn(f, 1.17549435e-38f);
            float e  = -__nv_logf(u);
            float g  = -__nv_logf(e);
            float sc = __fadd_rn(d_logp[v], g);
            unsigned sb = __float_as_uint(sc);
            sb = (sb & 0x80000000u) ? ~sb : (sb | 0x80000000u);
            kk = ((unsigned long long)sb << 32)
               | (unsigned long long)(0xFFFFFFFFu - (unsigned)v);
        }
        key[s] = kk;
    }
    __syncthreads();

    for (int kk2 = 2; kk2 <= sz; kk2 <<= 1) {
        for (int j = kk2 >> 1; j > 0; j >>= 1) {
            for (int i = threadIdx.x; i < sz; i += 512) {
                int l = i ^ j;
                if (l > i) {
                    unsigned long long a = key[i], c = key[l];
                    bool up = ((i & kk2) == 0);
                    if ((a > c) == up) { key[i] = c; key[l] = a; }
                }
            }
            __syncthreads();
        }
    }

    if (threadIdx.x < NEG) {
        unsigned long long kk = key[sz - 1 - threadIdx.x];
        unsigned v = 0xFFFFFFFFu - (unsigned)(kk & 0xFFFFFFFFull);
        if (v >= VV) v = 0;
        negs[threadIdx.x] = (int)v;
    }
    __syncthreads();

    // ---- negative dots: 16 warps x 4 rows each ----
    const int warp = threadIdx.x >> 5;     // 0..15
    const int lane = threadIdx.x & 31;
    const float4* ctr4 = (const float4*)ctr;
#pragma unroll
    for (int it = 0; it < 4; it++) {
        const int jn = it * 16 + warp;     // 0..63
        const float4* row4 = (const float4*)(Wx + (size_t)negs[jn] * DD);
        float acc = 0.0f;
#pragma unroll
        for (int t = 0; t < 4; t++) {
            float4 r = row4[lane + 32 * t];
            float4 c = ctr4[lane + 32 * t];
            acc += r.x * c.x + r.y * c.y + r.z * c.z + r.w * c.w;
        }
#pragma unroll
        for (int d2 = 16; d2 > 0; d2 >>= 1)
            acc += __shfl_down_sync(0xFFFFFFFFu, acc, d2);
        if (lane == 0) out[BB * CC + b * NEG + jn] = acc;
    }
}

// ---------------------------------------------------------------------------
extern "C" void kernel_launch(void* const* d_in, const int* in_sizes, int n_in,
                              void* d_out, int out_size) {
    const int*   center_ids  = (const int*)d_in[0];
    const int*   context_ids = (const int*)d_in[1];
    const float* W_center    = (const float*)d_in[2];
    const float* W_context   = (const float*)d_in[3];
    const float* sample_prob = (const float*)d_in[4];
    float* out = (float*)d_out;

    k0_tables<<<(VV + 255) / 256, 256>>>(sample_prob);

    dim3 g1(HASH_CTAS + 3, BB);   // 25 hash CTAs + 3 positive-dot CTAs per row
    k1_fused<<<g1, 256>>>(1u, center_ids, context_ids, W_center, out);

    k2_fused<<<BB, 512>>>(1u, center_ids, W_center, W_context, out);
}

// round 16
// speedup vs baseline: 1.0243x; 1.0243x over previous
#include <cuda_runtime.h>
#include <cstdint>

// ---------------------------------------------------------------------------
// SkipGram negative-sampling: bit-exact JAX threefry gumbel top-k + dot products
// V=100000, D=512, B=1024, C=20, NEG=64
// LOCKED CONFIG (R12): measured 281.9us.
//  k0: logp + conservative integer prefilter thresholds (MUFU).
//  k1: 25 hash CTAs/row (threefry at alu-pipe floor) + 3 positive-dot CTAs
//      hidden under hash compute.
//  k2: per-row exact rescore + bitonic top-64 + negative gather (DRAM floor).
// ---------------------------------------------------------------------------

#define VV   100000
#define DD   512
#define BB   1024
#define CC   20
#define NEG  64
#define CAP  384
#define T0   (-5.0)        // prefilter: mean survivors ~e^5.05 ~ 156/row
#define HASH_CTAS 25       // 25*256*16 = 102400 >= VV

extern "C" __device__ float __nv_logf(float);

// -------- static scratch --------
__device__ float    d_logp[VV];
__device__ unsigned d_thresh[VV];
__device__ int      d_cnt[BB];
__device__ int      d_cand_v[BB * CAP];

// ---------------------------------------------------------------------------
// threefry2x32, key (0,42). Round add forced to IMAD (fma pipe) via opaque
// `one`; alu pipe carries exactly 20 SHF + 20 LOP3 (measured floor).
// ---------------------------------------------------------------------------
#define TFR(r) { x0 = x0 * one + x1; x1 = __funnelshift_l(x1, x1, (r)) ^ x0; }

__device__ __forceinline__ unsigned tf_bits(unsigned ctr, unsigned one) {
    const unsigned ks1 = 42u, ks2 = 0x1BD11BF0u;   // 0x1BD11BDA ^ 42
    unsigned x0 = 0u;
    unsigned x1 = ctr + ks1;
    TFR(13) TFR(15) TFR(26) TFR(6)
    x0 += ks1; x1 += ks2 + 1u;
    TFR(17) TFR(29) TFR(16) TFR(24)
    x0 += ks2; x1 += 2u;
    TFR(13) TFR(15) TFR(26) TFR(6)
    x1 += ks1 + 3u;
    TFR(17) TFR(29) TFR(16) TFR(24)
    x0 += ks1; x1 += ks2 + 4u;
    TFR(13) TFR(15) TFR(26) TFR(6)
    x0 += ks2; x1 += 5u;
    return x0 ^ x1;
}

// ---------------------------------------------------------------------------
// k0: per-word logp (exact f32, used by rescoring) + conservative integer
// prefilter threshold — MUFU path, margin 0.05 in score space plus an 8-ulp
// guard, both strictly enlarging the candidate set. Zeroes cnt.
// ---------------------------------------------------------------------------
__global__ __launch_bounds__(256) void k0_tables(const float* __restrict__ p) {
    int v = blockIdx.x * 256 + threadIdx.x;
    if (v < BB) d_cnt[v] = 0;
    if (v >= VV) return;
    float pf = p[v];
    float lp = __nv_logf(pf);
    d_logp[v] = lp;
    float E = __expf(lp - (float)(T0 - 0.05));
    float ucrit = __expf(-E);
    int m = (int)floorf(ucrit * 8388608.0f) - 8;
    if (m < 0) m = 0;
    if (m > 8388607) m = 8388607;
    d_thresh[v] = ((unsigned)m) << 9;
}

// ---------------------------------------------------------------------------
// k1 (hash + positive dots): grid (HASH_CTAS+3, B), launch_bounds(256,6).
//  x <  HASH_CTAS : hash path — 16 v/thread in 4-hash groups, compute-and-
//                   discard threefry, per-survivor atomicAdd (~0.4/warp).
//  x >= HASH_CTAS : positive-dot CTAs (memory-bound, overlap hashing).
// ---------------------------------------------------------------------------
__global__ __launch_bounds__(256, 6) void k1_fused(unsigned one,
                                                const int* __restrict__ center_ids,
                                                const int* __restrict__ context_ids,
                                                const float* __restrict__ Wc,
                                                float* __restrict__ out) {
    const int b = blockIdx.y;

    if (blockIdx.x >= HASH_CTAS) {
        // ---- positive dots ----
        __shared__ __align__(16) float s_ctr[DD];
        const int k = blockIdx.x - HASH_CTAS;           // 0..2
        const size_t crow = (size_t)center_ids[b] * DD;
        for (int i = threadIdx.x; i < DD; i += 256) s_ctr[i] = Wc[crow + i];
        __syncthreads();
        const int warp = threadIdx.x >> 5;
        const int lane = threadIdx.x & 31;
        const int j = k * 8 + warp;
        if (j < CC) {
            const float4* row4 = (const float4*)(Wc + (size_t)context_ids[b * CC + j] * DD);
            const float4* ctr4 = (const float4*)s_ctr;
            float acc = 0.0f;
#pragma unroll
            for (int t = 0; t < 4; t++) {
                float4 r = row4[lane + 32 * t];
                float4 c = ctr4[lane + 32 * t];
                acc += r.x * c.x + r.y * c.y + r.z * c.z + r.w * c.w;
            }
#pragma unroll
            for (int d2 = 16; d2 > 0; d2 >>= 1)
                acc += __shfl_down_sync(0xFFFFFFFFu, acc, d2);
            if (lane == 0) out[b * CC + j] = acc;
        }
        return;
    }

    // ---- hash path: 16 consecutive v per thread, 4-hash groups ----
    const int tg = blockIdx.x * 256 + threadIdx.x;
    const int v0 = tg * 16;
    if (v0 >= VV) return;                   // VV % 16 == 0: per-thread uniform

    const unsigned base = (unsigned)b * (unsigned)VV + (unsigned)v0;
#pragma unroll
    for (int q = 0; q < 4; q++) {
        const uint4 t = *(const uint4*)&d_thresh[v0 + 4 * q];
        unsigned bits;
        bits = tf_bits(base + (unsigned)(4 * q + 0), one);
        if (bits >= t.x) {
            int pos = atomicAdd(&d_cnt[b], 1);
            if (pos < CAP) d_cand_v[b * CAP + pos] = v0 + 4 * q + 0;
        }
        bits = tf_bits(base + (unsigned)(4 * q + 1), one);
        if (bits >= t.y) {
            int pos = atomicAdd(&d_cnt[b], 1);
            if (pos < CAP) d_cand_v[b * CAP + pos] = v0 + 4 * q + 1;
        }
        bits = tf_bits(base + (unsigned)(4 * q + 2), one);
        if (bits >= t.z) {
            int pos = atomicAdd(&d_cnt[b], 1);
            if (pos < CAP) d_cand_v[b * CAP + pos] = v0 + 4 * q + 2;
        }
        bits = tf_bits(base + (unsigned)(4 * q + 3), one);
        if (bits >= t.w) {
            int pos = atomicAdd(&d_cnt[b], 1);
            if (pos < CAP) d_cand_v[b * CAP + pos] = v0 + 4 * q + 3;
        }
    }
}

// ---------------------------------------------------------------------------
// k2 (fused select + negative dots): one 256-thread CTA per b.
//  1. recompute hash per candidate, exact reference-f32 rescoring
//  2. bitonic top-64 over padded size sz (usually 256)
//     key = ordered(score)<<32 | ~v: score desc, index asc (XLA tie-break)
//  3. 8 warps x 8 rows stream the 64 negative rows of W_context.
// ---------------------------------------------------------------------------
__global__ __launch_bounds__(256) void k2_fused(unsigned one,
                                                const int* __restrict__ center_ids,
                                                const float* __restrict__ Wc,
                                                const float* __restrict__ Wx,
                                                float* __restrict__ out) {
    __shared__ __align__(16) unsigned long long key[CAP < 512 ? 512 : CAP];
    __shared__ __align__(16) float ctr[DD];
    __shared__ __align__(16) int   negs[NEG];
    const int b = blockIdx.x;
    int n = d_cnt[b];
    if (n > CAP) n = CAP;

    int sz = 64;
    while (sz < n) sz <<= 1;               // usually 256

    // center row -> smem (overlaps with candidate rescoring)
    const size_t crow = (size_t)center_ids[b] * DD;
    for (int i = threadIdx.x; i < DD; i += 256) ctr[i] = Wc[crow + i];

    for (int s = threadIdx.x; s < sz; s += 256) {
        unsigned long long kk = 0ull;
        if (s < n) {
            int v = d_cand_v[b * CAP + s];
            unsigned bits = tf_bits((unsigned)b * (unsigned)VV + (unsigned)v, one);
            unsigned m = bits >> 9;
            float f  = __fadd_rn(__uint_as_float(m | 0x3f800000u), -1.0f);
            float u  = __fadd_rn(f, 1.17549435e-38f);
            float e  = -__nv_logf(u);
            float g  = -__nv_logf(e);
            float sc = __fadd_rn(d_logp[v], g);
            unsigned sb = __float_as_uint(sc);
            sb = (sb & 0x80000000u) ? ~sb : (sb | 0x80000000u);
            kk = ((unsigned long long)sb << 32)
               | (unsigned long long)(0xFFFFFFFFu - (unsigned)v);
        }
        key[s] = kk;
    }
    __syncthreads();

    for (int kk2 = 2; kk2 <= sz; kk2 <<= 1) {
        for (int j = kk2 >> 1; j > 0; j >>= 1) {
            for (int i = threadIdx.x; i < sz; i += 256) {
                int l = i ^ j;
                if (l > i) {
                    unsigned long long a = key[i], c = key[l];
                    bool up = ((i & kk2) == 0);
                    if ((a > c) == up) { key[i] = c; key[l] = a; }
                }
            }
            __syncthreads();
        }
    }

    if (threadIdx.x < NEG) {
        unsigned long long kk = key[sz - 1 - threadIdx.x];
        unsigned v = 0xFFFFFFFFu - (unsigned)(kk & 0xFFFFFFFFull);
        if (v >= VV) v = 0;
        negs[threadIdx.x] = (int)v;
    }
    __syncthreads();

    // ---- negative dots: 8 warps x 8 rows each ----
    const int warp = threadIdx.x >> 5;
    const int lane = threadIdx.x & 31;
    const float4* ctr4 = (const float4*)ctr;
#pragma unroll
    for (int it = 0; it < 8; it++) {
        const int jn = it * 8 + warp;      // 0..63
        const float4* row4 = (const float4*)(Wx + (size_t)negs[jn] * DD);
        float acc = 0.0f;
#pragma unroll
        for (int t = 0; t < 4; t++) {
            float4 r = row4[lane + 32 * t];
            float4 c = ctr4[lane + 32 * t];
            acc += r.x * c.x + r.y * c.y + r.z * c.z + r.w * c.w;
        }
#pragma unroll
        for (int d2 = 16; d2 > 0; d2 >>= 1)
            acc += __shfl_down_sync(0xFFFFFFFFu, acc, d2);
        if (lane == 0) out[BB * CC + b * NEG + jn] = acc;
    }
}

// ---------------------------------------------------------------------------
extern "C" void kernel_launch(void* const* d_in, const int* in_sizes, int n_in,
                              void* d_out, int out_size) {
    const int*   center_ids  = (const int*)d_in[0];
    const int*   context_ids = (const int*)d_in[1];
    const float* W_center    = (const float*)d_in[2];
    const float* W_context   = (const float*)d_in[3];
    const float* sample_prob = (const float*)d_in[4];
    float* out = (float*)d_out;

    k0_tables<<<(VV + 255) / 256, 256>>>(sample_prob);

    dim3 g1(HASH_CTAS + 3, BB);   // 25 hash CTAs + 3 positive-dot CTAs per row
    k1_fused<<<g1, 256>>>(1u, center_ids, context_ids, W_center, out);

    k2_fused<<<BB, 256>>>(1u, center_ids, W_center, W_context, out);
}